// round 13
// baseline (speedup 1.0000x reference)
#include <cuda_runtime.h>

#define B_   32
#define C_   256
#define H_   80
#define W_   80
#define HWv  6400
#define MID_ 64
#define H2_  160
#define W2_  160

// Scratch: per (b, subpixel o in 0..3, h, w) the clipped source-space sample coord (ix, iy).
__device__ float2 g_coords[B_ * 4 * HWv];

__device__ __forceinline__ unsigned long long pack2(float lo, float hi) {
    unsigned long long r;
    asm("mov.b64 %0, {%1, %2};" : "=l"(r) : "f"(lo), "f"(hi));
    return r;
}
__device__ __forceinline__ void unpack2(unsigned long long v, float& lo, float& hi) {
    asm("mov.b64 {%0, %1}, %2;" : "=f"(lo), "=f"(hi) : "l"(v));
}
// Packed fp32x2 FMA (Blackwell; PTX-only, ptxas never auto-fuses).
__device__ __forceinline__ unsigned long long ffma2(unsigned long long a,
                                                    unsigned long long b,
                                                    unsigned long long c) {
    unsigned long long d;
    asm("fma.rn.f32x2 %0, %1, %2, %3;" : "=l"(d) : "l"(a), "l"(b), "l"(c));
    return d;
}

// ---------------------------------------------------------------------------
// Kernel A: per input pixel compute hid = relu(W1 x), off = tanh(W2 hid + b2),
// then the 4 subpixel sample coordinates (clipped to [0, 79]).
// 256 threads/block, 2 pixels/thread, W1 in shared as f32x2 pairs [c][m/2].
// ---------------------------------------------------------------------------
__global__ __launch_bounds__(256, 1)
void dysample_offsets(const float* __restrict__ x, const float* __restrict__ w1,
                      const float* __restrict__ w2, const float* __restrict__ b2) {
    extern __shared__ unsigned long long smem_u64[];
    unsigned long long* sw1 = smem_u64;                 // [256][32] packed pairs (64 KB)
    float* sw2 = (float*)(smem_u64 + C_ * 32);          // [8][64]
    float* sb2 = sw2 + 8 * 64;                          // [8]

    const int t = threadIdx.x;
    for (int idx = t; idx < C_ * 32; idx += 256) {
        int c = idx >> 5, m2 = idx & 31;
        sw1[idx] = pack2(w1[(2 * m2) * C_ + c], w1[(2 * m2 + 1) * C_ + c]);
    }
    for (int idx = t; idx < 512; idx += 256) sw2[idx] = w2[idx];
    if (t < 8) sb2[t] = b2[t];
    __syncthreads();

    const int P0 = blockIdx.x * 512 + t;   // 400 blocks * 512 pixels = 204800
    const int P1 = P0 + 256;
    const int b0 = P0 / HWv, p0 = P0 - b0 * HWv;
    const int b1 = P1 / HWv, p1 = P1 - b1 * HWv;
    const float* xp0 = x + (size_t)b0 * C_ * HWv + p0;
    const float* xp1 = x + (size_t)b1 * C_ * HWv + p1;

    unsigned long long acc0[32], acc1[32];
    #pragma unroll
    for (int m2 = 0; m2 < 32; m2++) { acc0[m2] = 0ULL; acc1[m2] = 0ULL; }

    // Software pipeline: prefetch next 8-channel x block while FMAing current.
    float cur0[8], cur1[8];
    #pragma unroll
    for (int k = 0; k < 8; k++) { cur0[k] = xp0[k * HWv]; cur1[k] = xp1[k * HWv]; }

    #pragma unroll 1
    for (int cb = 0; cb < C_; cb += 8) {
        float nxt0[8], nxt1[8];
        if (cb + 8 < C_) {
            #pragma unroll
            for (int k = 0; k < 8; k++) {
                nxt0[k] = xp0[(cb + 8 + k) * HWv];
                nxt1[k] = xp1[(cb + 8 + k) * HWv];
            }
        }
        #pragma unroll
        for (int k = 0; k < 8; k++) {
            unsigned long long xv0 = pack2(cur0[k], cur0[k]);
            unsigned long long xv1 = pack2(cur1[k], cur1[k]);
            const unsigned long long* wrow = sw1 + (cb + k) * 32;
            #pragma unroll
            for (int m2 = 0; m2 < 32; m2++) {
                unsigned long long wv = wrow[m2];   // one LDS.64 serves 2 FFMA2
                acc0[m2] = ffma2(xv0, wv, acc0[m2]);
                acc1[m2] = ffma2(xv1, wv, acc1[m2]);
            }
        }
        #pragma unroll
        for (int k = 0; k < 8; k++) { cur0[k] = nxt0[k]; cur1[k] = nxt1[k]; }
    }

    // ReLU in place.
    #pragma unroll
    for (int m2 = 0; m2 < 32; m2++) {
        float lo, hi;
        unpack2(acc0[m2], lo, hi);
        acc0[m2] = pack2(fmaxf(lo, 0.f), fmaxf(hi, 0.f));
        unpack2(acc1[m2], lo, hi);
        acc1[m2] = pack2(fmaxf(lo, 0.f), fmaxf(hi, 0.f));
    }

    // Stage 2: off[o] = tanh(W2[o,:] . hid + b2[o]),  o=0..3 -> off_x, 4..7 -> off_y
    float off0[8], off1[8];
    #pragma unroll
    for (int o = 0; o < 8; o++) {
        float s0 = sb2[o], s1 = s0;
        const float* wr = sw2 + o * 64;
        #pragma unroll
        for (int m2 = 0; m2 < 32; m2++) {
            float lo, hi;
            unpack2(acc0[m2], lo, hi);
            s0 = fmaf(lo, wr[2 * m2], s0);
            s0 = fmaf(hi, wr[2 * m2 + 1], s0);
            unpack2(acc1[m2], lo, hi);
            s1 = fmaf(lo, wr[2 * m2], s1);
            s1 = fmaf(hi, wr[2 * m2 + 1], s1);
        }
        off0[o] = tanhf(s0);
        off1[o] = tanhf(s1);
    }

    // Sample coords.
    // x2 = 2w+j : sx = (2*x2+1)/160 - 1 + off_x * (2/160)
    // ix = clip((sx+1)*0.5*79) = (4w+2j+1)*(39.5/160) + off_x*(79/160), clipped [0,79].
    const float A = 0.246875f;   // 39.5/160
    const float Bc = 0.49375f;   // 79/160
    const int h0 = p0 / W_, w0 = p0 - h0 * W_;
    const int h1 = p1 / W_, w1c = p1 - h1 * W_;
    #pragma unroll
    for (int o = 0; o < 4; o++) {
        int j = o & 1, i = o >> 1;
        float ix, iy;
        ix = fminf(fmaxf((float)(4 * w0 + 2 * j + 1) * A + off0[o] * Bc, 0.f), 79.f);
        iy = fminf(fmaxf((float)(4 * h0 + 2 * i + 1) * A + off0[o + 4] * Bc, 0.f), 79.f);
        g_coords[(b0 * 4 + o) * HWv + p0] = make_float2(ix, iy);
        ix = fminf(fmaxf((float)(4 * w1c + 2 * j + 1) * A + off1[o] * Bc, 0.f), 79.f);
        iy = fminf(fmaxf((float)(4 * h1 + 2 * i + 1) * A + off1[o + 4] * Bc, 0.f), 79.f);
        g_coords[(b1 * 4 + o) * HWv + p1] = make_float2(ix, iy);
    }
}

// ---------------------------------------------------------------------------
// Kernel B (v2): shared-staged bilinear gather with float2-pair slots.
//   slot[r][xi] = (x[row][xi], x[row][min(xi+1,79)])  -> one LDS.64 fetches a
//   horizontal tap pair, so each output needs 2 LDS.64 instead of 4 LDG.32.
// Block: 640 threads, output tile 160 (full width) x 16 rows, 64 channels
// (grid.z selects channel group). 11 staged input rows cover the tile because
// |offset| <= 0.494 source pixels. Double-buffered staging, LDG prefetch of
// the next channel overlapped with the gather of the current one.
// ---------------------------------------------------------------------------
#define TROWS 11
#define TPITCH 81          // 80 slots + 1 pad for bank stagger

__global__ __launch_bounds__(640)
void dysample_sample2(const float* __restrict__ x, float* __restrict__ out) {
    __shared__ float2 buf[2][TROWS * TPITCH];

    const int t  = threadIdx.x;
    const int Y  = blockIdx.x * 16;          // first output row of tile
    const int b  = blockIdx.y;
    const int cg = blockIdx.z;               // channel group (64 channels)
    // lowest possible y0 in tile: floor(0.49375*Y - 0.246875); never hits an integer.
    const int rlo = (int)floorf((2.f * Y - 1.f) * 0.246875f);

    // ---- staging slot assignment (2 slots/thread; thread >=240 duplicates) ----
    int sdst[2], gof0[2], gof1[2];
    #pragma unroll
    for (int s = 0; s < 2; s++) {
        int sid = t + 640 * s;
        if (sid >= 880) sid = t;             // duplicate write of identical value: benign
        int r = sid / 80, xi = sid - r * 80;
        int src = min(max(rlo + r, 0), 79);
        sdst[s] = r * TPITCH + xi;
        gof0[s] = src * W_ + xi;
        gof1[s] = src * W_ + min(xi + 1, 79);
    }

    // ---- per-output coords/weights (2 pairs of 2 adjacent x2 per thread) ----
    int   i0[2][2], i1[2][2];
    float wt[2][2][4];
    float* optr[2];
    const size_t HW2 = (size_t)H2_ * W2_;
    #pragma unroll
    for (int k = 0; k < 2; k++) {
        int pidx = t + 640 * k;              // 0..1279 pairs
        int row = pidx / 80, g = pidx - row * 80;
        int y2 = Y + row, x2 = 2 * g;
        int h = y2 >> 1, w = g;
        #pragma unroll
        for (int j = 0; j < 2; j++) {
            int o = ((y2 & 1) << 1) | j;
            float2 cd = g_coords[(b * 4 + o) * HWv + h * W_ + w];
            float fx = floorf(cd.x), fy = floorf(cd.y);
            int x0 = (int)fx, y0 = (int)fy;
            int y1c = min(y0 + 1, H_ - 1);
            float wx = cd.x - fx, wy = cd.y - fy;
            i0[k][j] = (y0 - rlo) * TPITCH + x0;
            i1[k][j] = (y1c - rlo) * TPITCH + x0;
            wt[k][j][0] = (1.f - wx) * (1.f - wy);
            wt[k][j][1] = wx * (1.f - wy);
            wt[k][j][2] = (1.f - wx) * wy;
            wt[k][j][3] = wx * wy;
        }
        optr[k] = out + (size_t)(b * C_ + cg * 64) * HW2 + (size_t)y2 * W2_ + x2;
    }

    const float* xc = x + (size_t)(b * C_ + cg * 64) * HWv;

    // ---- stage channel 0 ----
    float a0[2], a1[2];
    #pragma unroll
    for (int s = 0; s < 2; s++) { a0[s] = xc[gof0[s]]; a1[s] = xc[gof1[s]]; }
    #pragma unroll
    for (int s = 0; s < 2; s++) buf[0][sdst[s]] = make_float2(a0[s], a1[s]);
    __syncthreads();

    #pragma unroll 1
    for (int c = 0; c < 64; c++) {
        const int cur = c & 1;
        // prefetch next channel's staging values (hides LDG latency under gather)
        if (c + 1 < 64) {
            const float* xn = xc + (size_t)(c + 1) * HWv;
            #pragma unroll
            for (int s = 0; s < 2; s++) { a0[s] = xn[gof0[s]]; a1[s] = xn[gof1[s]]; }
        }
        // gather + store
        const float2* tb = buf[cur];
        #pragma unroll
        for (int k = 0; k < 2; k++) {
            float v[2];
            #pragma unroll
            for (int j = 0; j < 2; j++) {
                float2 aa = tb[i0[k][j]];    // (v00, v01) in one LDS.64
                float2 bb = tb[i1[k][j]];    // (v10, v11)
                v[j] = aa.x * wt[k][j][0] + aa.y * wt[k][j][1]
                     + bb.x * wt[k][j][2] + bb.y * wt[k][j][3];
            }
            *(float2*)(optr[k] + (size_t)c * HW2) = make_float2(v[0], v[1]);
        }
        // stage next channel into the other buffer (it was last read 2 channels ago)
        if (c + 1 < 64) {
            #pragma unroll
            for (int s = 0; s < 2; s++) buf[cur ^ 1][sdst[s]] = make_float2(a0[s], a1[s]);
        }
        __syncthreads();
    }
}

extern "C" void kernel_launch(void* const* d_in, const int* in_sizes, int n_in,
                              void* d_out, int out_size) {
    const float* x  = (const float*)d_in[0];
    const float* w1 = (const float*)d_in[1];
    const float* w2 = (const float*)d_in[2];
    const float* b2 = (const float*)d_in[3];
    float* out = (float*)d_out;

    const int smemA = C_ * 32 * 8 + 512 * 4 + 8 * 4;   // 67616 bytes
    cudaFuncSetAttribute(dysample_offsets,
                         cudaFuncAttributeMaxDynamicSharedMemorySize, smemA);

    dysample_offsets<<<400, 256, smemA>>>(x, w1, w2, b2);

    dim3 gridB(10, 32, 4);   // y-tiles, batch, channel groups
    dysample_sample2<<<gridB, 640>>>(x, out);
}

// round 14
// speedup vs baseline: 1.3556x; 1.3556x over previous
#include <cuda_runtime.h>

#define B_   32
#define C_   256
#define H_   80
#define W_   80
#define HWv  6400
#define MID_ 64
#define H2_  160
#define W2_  160

// Scratch: per (b, subpixel o in 0..3, h, w) the clipped source-space sample coord (ix, iy).
__device__ float2 g_coords[B_ * 4 * HWv];

__device__ __forceinline__ unsigned long long pack2(float lo, float hi) {
    unsigned long long r;
    asm("mov.b64 %0, {%1, %2};" : "=l"(r) : "f"(lo), "f"(hi));
    return r;
}
__device__ __forceinline__ void unpack2(unsigned long long v, float& lo, float& hi) {
    asm("mov.b64 {%0, %1}, %2;" : "=f"(lo), "=f"(hi) : "l"(v));
}
// Packed fp32x2 FMA (Blackwell; PTX-only, ptxas never auto-fuses).
__device__ __forceinline__ unsigned long long ffma2(unsigned long long a,
                                                    unsigned long long b,
                                                    unsigned long long c) {
    unsigned long long d;
    asm("fma.rn.f32x2 %0, %1, %2, %3;" : "=l"(d) : "l"(a), "l"(b), "l"(c));
    return d;
}

// ---------------------------------------------------------------------------
// Kernel A: per input pixel compute hid = relu(W1 x), off = tanh(W2 hid + b2),
// then the 4 subpixel sample coordinates (clipped to [0, 79]).
// 256 threads/block, 2 pixels/thread, W1 in shared as f32x2 pairs [c][m/2].
// ---------------------------------------------------------------------------
__global__ __launch_bounds__(256, 1)
void dysample_offsets(const float* __restrict__ x, const float* __restrict__ w1,
                      const float* __restrict__ w2, const float* __restrict__ b2) {
    extern __shared__ unsigned long long smem_u64[];
    unsigned long long* sw1 = smem_u64;                 // [256][32] packed pairs (64 KB)
    float* sw2 = (float*)(smem_u64 + C_ * 32);          // [8][64]
    float* sb2 = sw2 + 8 * 64;                          // [8]

    const int t = threadIdx.x;
    for (int idx = t; idx < C_ * 32; idx += 256) {
        int c = idx >> 5, m2 = idx & 31;
        sw1[idx] = pack2(w1[(2 * m2) * C_ + c], w1[(2 * m2 + 1) * C_ + c]);
    }
    for (int idx = t; idx < 512; idx += 256) sw2[idx] = w2[idx];
    if (t < 8) sb2[t] = b2[t];
    __syncthreads();

    const int P0 = blockIdx.x * 512 + t;   // 400 blocks * 512 pixels = 204800
    const int P1 = P0 + 256;
    const int b0 = P0 / HWv, p0 = P0 - b0 * HWv;
    const int b1 = P1 / HWv, p1 = P1 - b1 * HWv;
    const float* xp0 = x + (size_t)b0 * C_ * HWv + p0;
    const float* xp1 = x + (size_t)b1 * C_ * HWv + p1;

    unsigned long long acc0[32], acc1[32];
    #pragma unroll
    for (int m2 = 0; m2 < 32; m2++) { acc0[m2] = 0ULL; acc1[m2] = 0ULL; }

    // Software pipeline: prefetch next 8-channel x block while FMAing current.
    float cur0[8], cur1[8];
    #pragma unroll
    for (int k = 0; k < 8; k++) { cur0[k] = xp0[k * HWv]; cur1[k] = xp1[k * HWv]; }

    #pragma unroll 1
    for (int cb = 0; cb < C_; cb += 8) {
        float nxt0[8], nxt1[8];
        if (cb + 8 < C_) {
            #pragma unroll
            for (int k = 0; k < 8; k++) {
                nxt0[k] = xp0[(cb + 8 + k) * HWv];
                nxt1[k] = xp1[(cb + 8 + k) * HWv];
            }
        }
        #pragma unroll
        for (int k = 0; k < 8; k++) {
            unsigned long long xv0 = pack2(cur0[k], cur0[k]);
            unsigned long long xv1 = pack2(cur1[k], cur1[k]);
            const unsigned long long* wrow = sw1 + (cb + k) * 32;
            #pragma unroll
            for (int m2 = 0; m2 < 32; m2++) {
                unsigned long long wv = wrow[m2];   // one LDS.64 serves 2 FFMA2
                acc0[m2] = ffma2(xv0, wv, acc0[m2]);
                acc1[m2] = ffma2(xv1, wv, acc1[m2]);
            }
        }
        #pragma unroll
        for (int k = 0; k < 8; k++) { cur0[k] = nxt0[k]; cur1[k] = nxt1[k]; }
    }

    // ReLU in place.
    #pragma unroll
    for (int m2 = 0; m2 < 32; m2++) {
        float lo, hi;
        unpack2(acc0[m2], lo, hi);
        acc0[m2] = pack2(fmaxf(lo, 0.f), fmaxf(hi, 0.f));
        unpack2(acc1[m2], lo, hi);
        acc1[m2] = pack2(fmaxf(lo, 0.f), fmaxf(hi, 0.f));
    }

    // Stage 2: off[o] = tanh(W2[o,:] . hid + b2[o]),  o=0..3 -> off_x, 4..7 -> off_y
    float off0[8], off1[8];
    #pragma unroll
    for (int o = 0; o < 8; o++) {
        float s0 = sb2[o], s1 = s0;
        const float* wr = sw2 + o * 64;
        #pragma unroll
        for (int m2 = 0; m2 < 32; m2++) {
            float lo, hi;
            unpack2(acc0[m2], lo, hi);
            s0 = fmaf(lo, wr[2 * m2], s0);
            s0 = fmaf(hi, wr[2 * m2 + 1], s0);
            unpack2(acc1[m2], lo, hi);
            s1 = fmaf(lo, wr[2 * m2], s1);
            s1 = fmaf(hi, wr[2 * m2 + 1], s1);
        }
        off0[o] = tanhf(s0);
        off1[o] = tanhf(s1);
    }

    // Sample coords.
    // x2 = 2w+j : sx = (2*x2+1)/160 - 1 + off_x * (2/160)
    // ix = clip((sx+1)*0.5*79) = (4w+2j+1)*(39.5/160) + off_x*(79/160), clipped [0,79].
    const float A = 0.246875f;   // 39.5/160
    const float Bc = 0.49375f;   // 79/160
    const int h0 = p0 / W_, w0 = p0 - h0 * W_;
    const int h1 = p1 / W_, w1c = p1 - h1 * W_;
    #pragma unroll
    for (int o = 0; o < 4; o++) {
        int j = o & 1, i = o >> 1;
        float ix, iy;
        ix = fminf(fmaxf((float)(4 * w0 + 2 * j + 1) * A + off0[o] * Bc, 0.f), 79.f);
        iy = fminf(fmaxf((float)(4 * h0 + 2 * i + 1) * A + off0[o + 4] * Bc, 0.f), 79.f);
        g_coords[(b0 * 4 + o) * HWv + p0] = make_float2(ix, iy);
        ix = fminf(fmaxf((float)(4 * w1c + 2 * j + 1) * A + off1[o] * Bc, 0.f), 79.f);
        iy = fminf(fmaxf((float)(4 * h1 + 2 * i + 1) * A + off1[o + 4] * Bc, 0.f), 79.f);
        g_coords[(b1 * 4 + o) * HWv + p1] = make_float2(ix, iy);
    }
}

// ---------------------------------------------------------------------------
// Kernel B (v3): shared-staged bilinear gather, float2-pair slots
//   slot[r][xi] = (x[row][xi], x[row][min(xi+1,79)])  -> (v00,v01) or (v10,v11)
//   in a single LDS.64.
// Block: 320 threads. Output tile: 160 (full width) x 8 rows -> only 7 staged
// input rows (|off| <= 0.494 src px). 128 channels per block, processed in
// sets of 4 with double-buffered smem: ONE __syncthreads per 4 channels,
// register prefetch of the next set hidden under the gather of the current.
// Occupancy: 10-warp blocks, ~60 regs -> up to 6 blocks/SM (vs 1 in v2).
// ---------------------------------------------------------------------------
#define TROWS 7
#define TPITCH 81          // 80 slots + 1 pad for bank stagger
#define CHSET 4

__global__ __launch_bounds__(320)
void dysample_sample3(const float* __restrict__ x, float* __restrict__ out) {
    __shared__ float2 buf[2][CHSET][TROWS * TPITCH];   // 36.3 KB

    const int t  = threadIdx.x;
    const int Y  = blockIdx.x * 8;           // first output row of tile
    const int b  = blockIdx.y;
    const int cg = blockIdx.z;               // channel group of 128
    const int rlo = (int)floorf(0.49375f * (float)Y - 0.246875f);

    // ---- staging slot assignment: 560 slots, <=2 per thread ----
    int sdst[2], gof0[2], gof1[2];
    #pragma unroll
    for (int s = 0; s < 2; s++) {
        int sid = t + 320 * s;
        if (sid >= 560) sid = t;             // duplicate write of identical value: benign
        int r = sid / 80, xi = sid - r * 80;
        int src = min(max(rlo + r, 0), H_ - 1);
        sdst[s] = r * TPITCH + xi;
        gof0[s] = src * W_ + xi;
        gof1[s] = src * W_ + min(xi + 1, W_ - 1);
    }

    // ---- per-output coords/weights: 2 pairs of 2 adjacent x2 per thread ----
    int   idx0[4], idx1[4];                  // q = k*2 + j
    float wa[4], wb[4], wc[4], wd[4];
    float* optr[2];
    const size_t HW2 = (size_t)H2_ * W2_;
    #pragma unroll
    for (int k = 0; k < 2; k++) {
        int pidx = t + 320 * k;              // 0..639 pairs
        int row = pidx / 80, g = pidx - row * 80;
        int y2 = Y + row, x2 = 2 * g;
        int h = y2 >> 1, w = g;
        #pragma unroll
        for (int j = 0; j < 2; j++) {
            int q = k * 2 + j;
            int o = ((y2 & 1) << 1) | j;
            float2 cd = g_coords[(b * 4 + o) * HWv + h * W_ + w];
            float fx = floorf(cd.x), fy = floorf(cd.y);
            int x0 = (int)fx, y0 = (int)fy;
            int y1c = min(y0 + 1, H_ - 1);
            float wx = cd.x - fx, wy = cd.y - fy;
            idx0[q] = (y0 - rlo) * TPITCH + x0;
            idx1[q] = (y1c - rlo) * TPITCH + x0;
            wa[q] = (1.f - wx) * (1.f - wy);
            wb[q] = wx * (1.f - wy);
            wc[q] = (1.f - wx) * wy;
            wd[q] = wx * wy;
        }
        optr[k] = out + (size_t)(b * C_ + cg * 128) * HW2 + (size_t)y2 * W2_ + x2;
    }

    const float* xcg = x + (size_t)(b * C_ + cg * 128) * HWv;

    // ---- prologue: load set 0 staging values into regs ----
    float a0[2 * CHSET], a1[2 * CHSET];
    #pragma unroll
    for (int ch = 0; ch < CHSET; ch++) {
        const float* xp = xcg + (size_t)ch * HWv;
        #pragma unroll
        for (int s = 0; s < 2; s++) {
            a0[ch * 2 + s] = xp[gof0[s]];
            a1[ch * 2 + s] = xp[gof1[s]];
        }
    }

    #pragma unroll 1
    for (int set = 0; set < 128 / CHSET; set++) {
        float2 (*bb)[TROWS * TPITCH] = buf[set & 1];
        // store staged set into smem
        #pragma unroll
        for (int ch = 0; ch < CHSET; ch++)
            #pragma unroll
            for (int s = 0; s < 2; s++)
                bb[ch][sdst[s]] = make_float2(a0[ch * 2 + s], a1[ch * 2 + s]);
        __syncthreads();

        // prefetch next set (LDG latency hidden under gather below)
        if (set + 1 < 128 / CHSET) {
            const float* xn = xcg + (size_t)(set + 1) * CHSET * HWv;
            #pragma unroll
            for (int ch = 0; ch < CHSET; ch++) {
                const float* xp = xn + (size_t)ch * HWv;
                #pragma unroll
                for (int s = 0; s < 2; s++) {
                    a0[ch * 2 + s] = xp[gof0[s]];
                    a1[ch * 2 + s] = xp[gof1[s]];
                }
            }
        }

        // gather 4 channels x 2 pairs (2 LDS.64 per output, STG.64 per pair)
        #pragma unroll
        for (int ch = 0; ch < CHSET; ch++) {
            const float2* tb = bb[ch];
            #pragma unroll
            for (int k = 0; k < 2; k++) {
                float v[2];
                #pragma unroll
                for (int j = 0; j < 2; j++) {
                    int q = k * 2 + j;
                    float2 p0 = tb[idx0[q]];     // (v00, v01)
                    float2 p1 = tb[idx1[q]];     // (v10, v11)
                    v[j] = p0.x * wa[q] + p0.y * wb[q] + p1.x * wc[q] + p1.y * wd[q];
                }
                *(float2*)(optr[k] + (size_t)(set * CHSET + ch) * HW2) =
                    make_float2(v[0], v[1]);
            }
        }
        // no trailing sync needed: next iteration's STS targets the OTHER
        // buffer, whose last readers finished before the sync above.
        __syncthreads();
    }
}

extern "C" void kernel_launch(void* const* d_in, const int* in_sizes, int n_in,
                              void* d_out, int out_size) {
    const float* x  = (const float*)d_in[0];
    const float* w1 = (const float*)d_in[1];
    const float* w2 = (const float*)d_in[2];
    const float* b2 = (const float*)d_in[3];
    float* out = (float*)d_out;

    const int smemA = C_ * 32 * 8 + 512 * 4 + 8 * 4;   // 67616 bytes
    cudaFuncSetAttribute(dysample_offsets,
                         cudaFuncAttributeMaxDynamicSharedMemorySize, smemA);

    dysample_offsets<<<400, 256, smemA>>>(x, w1, w2, b2);

    dim3 gridB(20, 32, 2);   // y-tiles, batch, channel groups of 128
    dysample_sample3<<<gridB, 320>>>(x, out);
}

// round 15
// speedup vs baseline: 1.3789x; 1.0172x over previous
#include <cuda_runtime.h>

#define B_   32
#define C_   256
#define H_   80
#define W_   80
#define HWv  6400
#define MID_ 64
#define H2_  160
#define W2_  160

// Scratch: per (b, subpixel o in 0..3, h, w) the clipped source-space sample coord (ix, iy).
__device__ float2 g_coords[B_ * 4 * HWv];

__device__ __forceinline__ unsigned long long pack2(float lo, float hi) {
    unsigned long long r;
    asm("mov.b64 %0, {%1, %2};" : "=l"(r) : "f"(lo), "f"(hi));
    return r;
}
__device__ __forceinline__ void unpack2(unsigned long long v, float& lo, float& hi) {
    asm("mov.b64 {%0, %1}, %2;" : "=f"(lo), "=f"(hi) : "l"(v));
}
// Packed fp32x2 FMA (Blackwell; PTX-only, ptxas never auto-fuses).
__device__ __forceinline__ unsigned long long ffma2(unsigned long long a,
                                                    unsigned long long b,
                                                    unsigned long long c) {
    unsigned long long d;
    asm("fma.rn.f32x2 %0, %1, %2, %3;" : "=l"(d) : "l"(a), "l"(b), "l"(c));
    return d;
}

// ---------------------------------------------------------------------------
// Kernel A: per input pixel compute hid = relu(W1 x), off = tanh(W2 hid + b2),
// then the 4 subpixel sample coordinates (clipped to [0, 79]).
// 256 threads/block, 2 pixels/thread, W1 in shared as f32x2 pairs [c][m/2].
// ---------------------------------------------------------------------------
__global__ __launch_bounds__(256, 1)
void dysample_offsets(const float* __restrict__ x, const float* __restrict__ w1,
                      const float* __restrict__ w2, const float* __restrict__ b2) {
    extern __shared__ unsigned long long smem_u64[];
    unsigned long long* sw1 = smem_u64;                 // [256][32] packed pairs (64 KB)
    float* sw2 = (float*)(smem_u64 + C_ * 32);          // [8][64]
    float* sb2 = sw2 + 8 * 64;                          // [8]

    const int t = threadIdx.x;
    for (int idx = t; idx < C_ * 32; idx += 256) {
        int c = idx >> 5, m2 = idx & 31;
        sw1[idx] = pack2(w1[(2 * m2) * C_ + c], w1[(2 * m2 + 1) * C_ + c]);
    }
    for (int idx = t; idx < 512; idx += 256) sw2[idx] = w2[idx];
    if (t < 8) sb2[t] = b2[t];
    __syncthreads();

    const int P0 = blockIdx.x * 512 + t;   // 400 blocks * 512 pixels = 204800
    const int P1 = P0 + 256;
    const int b0 = P0 / HWv, p0 = P0 - b0 * HWv;
    const int b1 = P1 / HWv, p1 = P1 - b1 * HWv;
    const float* xp0 = x + (size_t)b0 * C_ * HWv + p0;
    const float* xp1 = x + (size_t)b1 * C_ * HWv + p1;

    unsigned long long acc0[32], acc1[32];
    #pragma unroll
    for (int m2 = 0; m2 < 32; m2++) { acc0[m2] = 0ULL; acc1[m2] = 0ULL; }

    // Software pipeline: prefetch next 8-channel x block while FMAing current.
    float cur0[8], cur1[8];
    #pragma unroll
    for (int k = 0; k < 8; k++) { cur0[k] = xp0[k * HWv]; cur1[k] = xp1[k * HWv]; }

    #pragma unroll 1
    for (int cb = 0; cb < C_; cb += 8) {
        float nxt0[8], nxt1[8];
        if (cb + 8 < C_) {
            #pragma unroll
            for (int k = 0; k < 8; k++) {
                nxt0[k] = xp0[(cb + 8 + k) * HWv];
                nxt1[k] = xp1[(cb + 8 + k) * HWv];
            }
        }
        #pragma unroll
        for (int k = 0; k < 8; k++) {
            unsigned long long xv0 = pack2(cur0[k], cur0[k]);
            unsigned long long xv1 = pack2(cur1[k], cur1[k]);
            const unsigned long long* wrow = sw1 + (cb + k) * 32;
            #pragma unroll
            for (int m2 = 0; m2 < 32; m2++) {
                unsigned long long wv = wrow[m2];   // one LDS.64 serves 2 FFMA2
                acc0[m2] = ffma2(xv0, wv, acc0[m2]);
                acc1[m2] = ffma2(xv1, wv, acc1[m2]);
            }
        }
        #pragma unroll
        for (int k = 0; k < 8; k++) { cur0[k] = nxt0[k]; cur1[k] = nxt1[k]; }
    }

    // ReLU in place.
    #pragma unroll
    for (int m2 = 0; m2 < 32; m2++) {
        float lo, hi;
        unpack2(acc0[m2], lo, hi);
        acc0[m2] = pack2(fmaxf(lo, 0.f), fmaxf(hi, 0.f));
        unpack2(acc1[m2], lo, hi);
        acc1[m2] = pack2(fmaxf(lo, 0.f), fmaxf(hi, 0.f));
    }

    // Stage 2: off[o] = tanh(W2[o,:] . hid + b2[o]),  o=0..3 -> off_x, 4..7 -> off_y
    float off0[8], off1[8];
    #pragma unroll
    for (int o = 0; o < 8; o++) {
        float s0 = sb2[o], s1 = s0;
        const float* wr = sw2 + o * 64;
        #pragma unroll
        for (int m2 = 0; m2 < 32; m2++) {
            float lo, hi;
            unpack2(acc0[m2], lo, hi);
            s0 = fmaf(lo, wr[2 * m2], s0);
            s0 = fmaf(hi, wr[2 * m2 + 1], s0);
            unpack2(acc1[m2], lo, hi);
            s1 = fmaf(lo, wr[2 * m2], s1);
            s1 = fmaf(hi, wr[2 * m2 + 1], s1);
        }
        off0[o] = tanhf(s0);
        off1[o] = tanhf(s1);
    }

    // Sample coords.
    // x2 = 2w+j : sx = (2*x2+1)/160 - 1 + off_x * (2/160)
    // ix = clip((sx+1)*0.5*79) = (4w+2j+1)*(39.5/160) + off_x*(79/160), clipped [0,79].
    const float A = 0.246875f;   // 39.5/160
    const float Bc = 0.49375f;   // 79/160
    const int h0 = p0 / W_, w0 = p0 - h0 * W_;
    const int h1 = p1 / W_, w1c = p1 - h1 * W_;
    #pragma unroll
    for (int o = 0; o < 4; o++) {
        int j = o & 1, i = o >> 1;
        float ix, iy;
        ix = fminf(fmaxf((float)(4 * w0 + 2 * j + 1) * A + off0[o] * Bc, 0.f), 79.f);
        iy = fminf(fmaxf((float)(4 * h0 + 2 * i + 1) * A + off0[o + 4] * Bc, 0.f), 79.f);
        g_coords[(b0 * 4 + o) * HWv + p0] = make_float2(ix, iy);
        ix = fminf(fmaxf((float)(4 * w1c + 2 * j + 1) * A + off1[o] * Bc, 0.f), 79.f);
        iy = fminf(fmaxf((float)(4 * h1 + 2 * i + 1) * A + off1[o + 4] * Bc, 0.f), 79.f);
        g_coords[(b1 * 4 + o) * HWv + p1] = make_float2(ix, iy);
    }
}

// ---------------------------------------------------------------------------
// Kernel B (v4): shared-staged bilinear gather, float2-pair slots, REG DIET.
//   slot[r][xi] = (x[row][xi], x[row][min(xi+1,79)])  -> one LDS.64 per tap row.
// Block: 320 threads, tile 160x8 outputs, 7 staged input rows. 128 channels
// per block in sets of CHSET=2, double-buffered smem, ONE sync per set.
// Register cuts vs v3 (96 regs -> target <=68 via __launch_bounds__(320,3)):
//   - CHSET 2 (prefetch 8 regs), smem 18.1 KB
//   - (wx,wy) + lerp instead of 4 precomputed weights (8 regs saved)
//   - packed (idx0 | dy*81 << 16) per tap (4 regs saved)
// -> 3 blocks/SM (30 warps) instead of 2 (20 warps).
// ---------------------------------------------------------------------------
#define TROWS 7
#define TPITCH 81          // 80 slots + 1 pad for bank stagger
#define CHSET 2

__global__ __launch_bounds__(320, 3)
void dysample_sample4(const float* __restrict__ x, float* __restrict__ out) {
    __shared__ float2 buf[2][CHSET][TROWS * TPITCH];   // 18.1 KB

    const int t  = threadIdx.x;
    const int Y  = blockIdx.x * 8;           // first output row of tile
    const int b  = blockIdx.y;
    const int cg = blockIdx.z;               // channel group of 128
    const int rlo = (int)floorf(0.49375f * (float)Y - 0.246875f);

    // ---- staging slot assignment: 560 slots, <=2 per thread ----
    int sdst[2], gof0[2], gof1[2];
    #pragma unroll
    for (int s = 0; s < 2; s++) {
        int sid = t + 320 * s;
        if (sid >= 560) sid = t;             // duplicate write of identical value: benign
        int r = sid / 80, xi = sid - r * 80;
        int src = min(max(rlo + r, 0), H_ - 1);
        sdst[s] = r * TPITCH + xi;
        gof0[s] = src * W_ + xi;
        gof1[s] = src * W_ + min(xi + 1, W_ - 1);
    }

    // ---- per-output state: 4 outputs/thread (2 pairs of 2 adjacent x2) ----
    int   pk[4];                             // idx0 | (dy*TPITCH) << 16
    float wx[4], wy[4];
    float* optr[2];
    const size_t HW2 = (size_t)H2_ * W2_;
    #pragma unroll
    for (int k = 0; k < 2; k++) {
        int pidx = t + 320 * k;              // 0..639 pairs
        int row = pidx / 80, g = pidx - row * 80;
        int y2 = Y + row, x2 = 2 * g;
        int h = y2 >> 1, w = g;
        #pragma unroll
        for (int j = 0; j < 2; j++) {
            int q = k * 2 + j;
            int o = ((y2 & 1) << 1) | j;
            float2 cd = g_coords[(b * 4 + o) * HWv + h * W_ + w];
            float fx = floorf(cd.x), fy = floorf(cd.y);
            int x0 = (int)fx, y0 = (int)fy;
            int y1c = min(y0 + 1, H_ - 1);
            pk[q] = ((y0 - rlo) * TPITCH + x0) | (((y1c - y0) * TPITCH) << 16);
            wx[q] = cd.x - fx;
            wy[q] = cd.y - fy;
        }
        optr[k] = out + (size_t)(b * C_ + cg * 128) * HW2 + (size_t)y2 * W2_ + x2;
    }

    const float* xcg = x + (size_t)(b * C_ + cg * 128) * HWv;

    // ---- prologue: load set 0 staging values ----
    float a0[2 * CHSET], a1[2 * CHSET];
    #pragma unroll
    for (int ch = 0; ch < CHSET; ch++) {
        const float* xp = xcg + (size_t)ch * HWv;
        #pragma unroll
        for (int s = 0; s < 2; s++) {
            a0[ch * 2 + s] = xp[gof0[s]];
            a1[ch * 2 + s] = xp[gof1[s]];
        }
    }

    #pragma unroll 1
    for (int set = 0; set < 128 / CHSET; set++) {
        float2 (*bb)[TROWS * TPITCH] = buf[set & 1];
        // store staged set into smem
        #pragma unroll
        for (int ch = 0; ch < CHSET; ch++)
            #pragma unroll
            for (int s = 0; s < 2; s++)
                bb[ch][sdst[s]] = make_float2(a0[ch * 2 + s], a1[ch * 2 + s]);
        __syncthreads();

        // prefetch next set (LDG latency hidden under gather below)
        if (set + 1 < 128 / CHSET) {
            const float* xn = xcg + (size_t)(set + 1) * CHSET * HWv;
            #pragma unroll
            for (int ch = 0; ch < CHSET; ch++) {
                const float* xp = xn + (size_t)ch * HWv;
                #pragma unroll
                for (int s = 0; s < 2; s++) {
                    a0[ch * 2 + s] = xp[gof0[s]];
                    a1[ch * 2 + s] = xp[gof1[s]];
                }
            }
        }

        // gather CHSET channels x 2 pairs; 2 LDS.64 + lerp per output
        #pragma unroll
        for (int ch = 0; ch < CHSET; ch++) {
            const float2* tb = bb[ch];
            #pragma unroll
            for (int k = 0; k < 2; k++) {
                float v[2];
                #pragma unroll
                for (int j = 0; j < 2; j++) {
                    int q = k * 2 + j;
                    int i0 = pk[q] & 0xFFFF;
                    int i1 = i0 + (pk[q] >> 16);
                    float2 p0 = tb[i0];              // (v00, v01)
                    float2 p1 = tb[i1];              // (v10, v11)
                    float top = fmaf(wx[q], p0.y - p0.x, p0.x);
                    float bot = fmaf(wx[q], p1.y - p1.x, p1.x);
                    v[j] = fmaf(wy[q], bot - top, top);
                }
                *(float2*)(optr[k] + (size_t)(set * CHSET + ch) * HW2) =
                    make_float2(v[0], v[1]);
            }
        }
        // No trailing sync: next iteration's STS targets the OTHER buffer;
        // its previous readers (set-1) finished before THIS set's sync.
    }
}

extern "C" void kernel_launch(void* const* d_in, const int* in_sizes, int n_in,
                              void* d_out, int out_size) {
    const float* x  = (const float*)d_in[0];
    const float* w1 = (const float*)d_in[1];
    const float* w2 = (const float*)d_in[2];
    const float* b2 = (const float*)d_in[3];
    float* out = (float*)d_out;

    const int smemA = C_ * 32 * 8 + 512 * 4 + 8 * 4;   // 67616 bytes
    cudaFuncSetAttribute(dysample_offsets,
                         cudaFuncAttributeMaxDynamicSharedMemorySize, smemA);

    dysample_offsets<<<400, 256, smemA>>>(x, w1, w2, b2);

    dim3 gridB(20, 32, 2);   // y-tiles, batch, channel groups of 128
    dysample_sample4<<<gridB, 320>>>(x, out);
}

// round 17
// speedup vs baseline: 1.5308x; 1.1102x over previous
#include <cuda_runtime.h>
#include <cstdint>

#define B_   32
#define C_   256
#define H_   80
#define W_   80
#define HWv  6400
#define MID_ 64
#define H2_  160
#define W2_  160

// Scratch: per (b, subpixel o in 0..3, h, w) the clipped source-space sample coord (ix, iy).
__device__ float2 g_coords[B_ * 4 * HWv];
// Packed TF32 W1 for mma.sync B-fragments:
//   g_w1p[((kt*4+tg)*8+nt)*8+gid] = ( tf32(W1[nt*8+gid][kt*8+tg]),
//                                     tf32(W1[nt*8+gid][kt*8+tg+4]) )
__device__ float2 g_w1p[32 * 4 * 8 * 8];   // 8192 float2 = 64 KB

__device__ __forceinline__ unsigned tf32_of(float f) {
    unsigned r;
    asm("cvt.rna.tf32.f32 %0, %1;" : "=r"(r) : "f"(f));
    return r;
}

// ---------------------------------------------------------------------------
// Kernel A0: pre-pack W1 into TF32 B-fragment pairs (runs every call; ~3 us).
// ---------------------------------------------------------------------------
__global__ void prep_w1(const float* __restrict__ w1) {
    int i = blockIdx.x * 256 + threadIdx.x;        // 0..8191
    int gid = i & 7;
    int nt  = (i >> 3) & 7;
    int tg  = (i >> 6) & 3;
    int kt  = i >> 8;
    int m = nt * 8 + gid;
    int c = kt * 8 + tg;
    float2 v;
    v.x = __uint_as_float(tf32_of(w1[m * C_ + c]));
    v.y = __uint_as_float(tf32_of(w1[m * C_ + c + 4]));
    g_w1p[i] = v;
}

// ---------------------------------------------------------------------------
// Kernel A1: TF32 mma.sync stage-1 GEMM + fp32 stage-2 + coords.
// Block 256 thr (8 warps). Warp handles 16 contiguous pixels:
//   hid[16 x 64] = x_tile[16 x 256] * W1^T  via m16n8k8, 32 k-steps x 8 n-tiles.
// Epilogue: relu, z = W2*hid + b2 (partial dot per lane over its 16 mids,
// shfl-reduce over the 4-lane quad), tanh, coords -> g_coords.
// ---------------------------------------------------------------------------
__global__ __launch_bounds__(256)
void dysample_offsets_mma(const float* __restrict__ x,
                          const float* __restrict__ w2,
                          const float* __restrict__ b2) {
    __shared__ float sw2[512];
    __shared__ float sb2[8];
    const int t = threadIdx.x;
    for (int i = t; i < 512; i += 256) sw2[i] = w2[i];   // FIX: was `if (t<512)` with 256 threads
    if (t < 8)  sb2[t] = b2[t];
    __syncthreads();

    const int warp = t >> 5, lane = t & 31;
    const int gid = lane >> 2, tg = lane & 3;          // groupID, thread-in-group
    const int P0 = blockIdx.x * 128 + warp * 16;       // 1600 blocks * 128 px
    const int b = P0 / HWv, p = P0 - b * HWv;          // blocks never straddle b
    const float* xb = x + (size_t)b * C_ * HWv + p;

    float d[8][4];
    #pragma unroll
    for (int nt = 0; nt < 8; nt++)
        #pragma unroll
        for (int q = 0; q < 4; q++) d[nt][q] = 0.f;

    // A-fragment source: rows = pixels p+gid / p+gid+8, cols = channels kt*8+tg(+4)
    const float* xc = xb + (size_t)tg * HWv;
    float af[4];
    af[0] = xc[gid];
    af[1] = xc[gid + 8];
    af[2] = xc[4 * (size_t)HWv + gid];
    af[3] = xc[4 * (size_t)HWv + gid + 8];

    #pragma unroll 1
    for (int kt = 0; kt < 32; kt++) {
        float nf[4];
        if (kt + 1 < 32) {
            const float* xn = xc + (size_t)(kt + 1) * 8 * HWv;
            nf[0] = xn[gid];
            nf[1] = xn[gid + 8];
            nf[2] = xn[4 * (size_t)HWv + gid];
            nf[3] = xn[4 * (size_t)HWv + gid + 8];
        }
        unsigned a0 = tf32_of(af[0]), a1 = tf32_of(af[1]);
        unsigned a2 = tf32_of(af[2]), a3 = tf32_of(af[3]);
        const float2* wp = g_w1p + ((kt * 4 + tg) * 8) * 8 + gid;
        #pragma unroll
        for (int nt = 0; nt < 8; nt++) {
            float2 bv = wp[nt * 8];
            unsigned bb0 = __float_as_uint(bv.x);
            unsigned bb1 = __float_as_uint(bv.y);
            asm volatile(
                "mma.sync.aligned.m16n8k8.row.col.f32.tf32.tf32.f32 "
                "{%0,%1,%2,%3}, {%4,%5,%6,%7}, {%8,%9}, {%0,%1,%2,%3};"
                : "+f"(d[nt][0]), "+f"(d[nt][1]), "+f"(d[nt][2]), "+f"(d[nt][3])
                : "r"(a0), "r"(a1), "r"(a2), "r"(a3), "r"(bb0), "r"(bb1));
        }
        #pragma unroll
        for (int q = 0; q < 4; q++) af[q] = nf[q];
    }

    // ReLU
    #pragma unroll
    for (int nt = 0; nt < 8; nt++)
        #pragma unroll
        for (int q = 0; q < 4; q++) d[nt][q] = fmaxf(d[nt][q], 0.f);

    // Stage 2: z[o] = W2[o,:].hid + b2[o].
    // Lane's mids: nt*8 + 2*tg + {0,1}. d[nt][0..1] -> pixel p+gid ; d[nt][2..3] -> p+gid+8.
    float za0[8], za1[8];
    #pragma unroll
    for (int o = 0; o < 8; o++) {
        float s0 = 0.f, s1 = 0.f;
        const float* wr = sw2 + o * 64 + 2 * tg;
        #pragma unroll
        for (int nt = 0; nt < 8; nt++) {
            float w0 = wr[nt * 8], w1v = wr[nt * 8 + 1];
            s0 = fmaf(d[nt][0], w0, s0); s0 = fmaf(d[nt][1], w1v, s0);
            s1 = fmaf(d[nt][2], w0, s1); s1 = fmaf(d[nt][3], w1v, s1);
        }
        s0 += __shfl_xor_sync(0xffffffffu, s0, 1);
        s0 += __shfl_xor_sync(0xffffffffu, s0, 2);
        s1 += __shfl_xor_sync(0xffffffffu, s1, 1);
        s1 += __shfl_xor_sync(0xffffffffu, s1, 2);
        za0[o] = s0 + sb2[o];
        za1[o] = s1 + sb2[o];
    }

    // Lane tg writes subpixel o = tg for its two pixels.
    float zx0 = za0[0], zy0 = za0[4], zx1 = za1[0], zy1 = za1[4];
    #pragma unroll
    for (int o = 1; o < 4; o++) {
        bool sel = (tg == o);
        zx0 = sel ? za0[o]     : zx0;
        zy0 = sel ? za0[o + 4] : zy0;
        zx1 = sel ? za1[o]     : zx1;
        zy1 = sel ? za1[o + 4] : zy1;
    }

    const float A = 0.246875f;   // 39.5/160
    const float Bc = 0.49375f;   // 79/160
    const int j = tg & 1, i2 = tg >> 1;
    {
        int ph = p + gid;
        int h = ph / W_, w = ph - h * W_;
        float ix = fminf(fmaxf((float)(4 * w + 2 * j + 1) * A + tanhf(zx0) * Bc, 0.f), 79.f);
        float iy = fminf(fmaxf((float)(4 * h + 2 * i2 + 1) * A + tanhf(zy0) * Bc, 0.f), 79.f);
        g_coords[(b * 4 + tg) * HWv + ph] = make_float2(ix, iy);
    }
    {
        int ph = p + gid + 8;
        int h = ph / W_, w = ph - h * W_;
        float ix = fminf(fmaxf((float)(4 * w + 2 * j + 1) * A + tanhf(zx1) * Bc, 0.f), 79.f);
        float iy = fminf(fmaxf((float)(4 * h + 2 * i2 + 1) * A + tanhf(zy1) * Bc, 0.f), 79.f);
        g_coords[(b * 4 + tg) * HWv + ph] = make_float2(ix, iy);
    }
}

// ---------------------------------------------------------------------------
// Kernel B (v4, unchanged): shared-staged bilinear gather, float2-pair slots.
// ---------------------------------------------------------------------------
#define TROWS 7
#define TPITCH 81
#define CHSET 2

__global__ __launch_bounds__(320, 3)
void dysample_sample4(const float* __restrict__ x, float* __restrict__ out) {
    __shared__ float2 buf[2][CHSET][TROWS * TPITCH];

    const int t  = threadIdx.x;
    const int Y  = blockIdx.x * 8;
    const int b  = blockIdx.y;
    const int cg = blockIdx.z;
    const int rlo = (int)floorf(0.49375f * (float)Y - 0.246875f);

    int sdst[2], gof0[2], gof1[2];
    #pragma unroll
    for (int s = 0; s < 2; s++) {
        int sid = t + 320 * s;
        if (sid >= 560) sid = t;
        int r = sid / 80, xi = sid - r * 80;
        int src = min(max(rlo + r, 0), H_ - 1);
        sdst[s] = r * TPITCH + xi;
        gof0[s] = src * W_ + xi;
        gof1[s] = src * W_ + min(xi + 1, W_ - 1);
    }

    int   pk[4];
    float wx[4], wy[4];
    float* optr[2];
    const size_t HW2 = (size_t)H2_ * W2_;
    #pragma unroll
    for (int k = 0; k < 2; k++) {
        int pidx = t + 320 * k;
        int row = pidx / 80, g = pidx - row * 80;
        int y2 = Y + row, x2 = 2 * g;
        int h = y2 >> 1, w = g;
        #pragma unroll
        for (int j = 0; j < 2; j++) {
            int q = k * 2 + j;
            int o = ((y2 & 1) << 1) | j;
            float2 cd = g_coords[(b * 4 + o) * HWv + h * W_ + w];
            float fx = floorf(cd.x), fy = floorf(cd.y);
            int x0 = (int)fx, y0 = (int)fy;
            int y1c = min(y0 + 1, H_ - 1);
            pk[q] = ((y0 - rlo) * TPITCH + x0) | (((y1c - y0) * TPITCH) << 16);
            wx[q] = cd.x - fx;
            wy[q] = cd.y - fy;
        }
        optr[k] = out + (size_t)(b * C_ + cg * 128) * HW2 + (size_t)y2 * W2_ + x2;
    }

    const float* xcg = x + (size_t)(b * C_ + cg * 128) * HWv;

    float a0[2 * CHSET], a1[2 * CHSET];
    #pragma unroll
    for (int ch = 0; ch < CHSET; ch++) {
        const float* xp = xcg + (size_t)ch * HWv;
        #pragma unroll
        for (int s = 0; s < 2; s++) {
            a0[ch * 2 + s] = xp[gof0[s]];
            a1[ch * 2 + s] = xp[gof1[s]];
        }
    }

    #pragma unroll 1
    for (int set = 0; set < 128 / CHSET; set++) {
        float2 (*bb)[TROWS * TPITCH] = buf[set & 1];
        #pragma unroll
        for (int ch = 0; ch < CHSET; ch++)
            #pragma unroll
            for (int s = 0; s < 2; s++)
                bb[ch][sdst[s]] = make_float2(a0[ch * 2 + s], a1[ch * 2 + s]);
        __syncthreads();

        if (set + 1 < 128 / CHSET) {
            const float* xn = xcg + (size_t)(set + 1) * CHSET * HWv;
            #pragma unroll
            for (int ch = 0; ch < CHSET; ch++) {
                const float* xp = xn + (size_t)ch * HWv;
                #pragma unroll
                for (int s = 0; s < 2; s++) {
                    a0[ch * 2 + s] = xp[gof0[s]];
                    a1[ch * 2 + s] = xp[gof1[s]];
                }
            }
        }

        #pragma unroll
        for (int ch = 0; ch < CHSET; ch++) {
            const float2* tb = bb[ch];
            #pragma unroll
            for (int k = 0; k < 2; k++) {
                float v[2];
                #pragma unroll
                for (int j = 0; j < 2; j++) {
                    int q = k * 2 + j;
                    int i0 = pk[q] & 0xFFFF;
                    int i1 = i0 + (pk[q] >> 16);
                    float2 p0 = tb[i0];
                    float2 p1 = tb[i1];
                    float top = fmaf(wx[q], p0.y - p0.x, p0.x);
                    float bot = fmaf(wx[q], p1.y - p1.x, p1.x);
                    v[j] = fmaf(wy[q], bot - top, top);
                }
                *(float2*)(optr[k] + (size_t)(set * CHSET + ch) * HW2) =
                    make_float2(v[0], v[1]);
            }
        }
    }
}

extern "C" void kernel_launch(void* const* d_in, const int* in_sizes, int n_in,
                              void* d_out, int out_size) {
    const float* x  = (const float*)d_in[0];
    const float* w1 = (const float*)d_in[1];
    const float* w2 = (const float*)d_in[2];
    const float* b2 = (const float*)d_in[3];
    float* out = (float*)d_out;

    prep_w1<<<32, 256>>>(w1);
    dysample_offsets_mma<<<1600, 256>>>(x, w2, b2);

    dim3 gridB(20, 32, 2);
    dysample_sample4<<<gridB, 320>>>(x, out);
}